// round 16
// baseline (speedup 1.0000x reference)
#include <cuda_runtime.h>

// ---------------------------------------------------------------------------
// G1 sub2+sub3 graph update.
//   Precompute: g_dst[e] = right_spec[s3col[e*deg3]]  (+ identity detection)
//               g_pack[e] = row3 indices packed 4x10 bits (when n_typ<=1024)
//               g_src[j] = left_spec[s2row[j]]
//   Phase A (types):    t_new[c] = emb[right_common[c]] + sum_seg emb[g_src] + (n_ent - deg2)
//   Phase B (entities): s[e] = (n_typ - deg3) + sum_seg t_new[row3]
//                       out[dst] = emb[dst] * (1 - s / (1 + deg3))
// Base: R12-passing kernel (57.4 us). Sole change: entity emb reads use
// default caching (__ldg) instead of __ldcs so the 103 MB emb table can stay
// L2-resident across graph replays; out writes stay __stcs (evict-first).
// ---------------------------------------------------------------------------

#define D_DIM    128
#define CHUNK    32          // entity kernel: floats per type per plane
#define N_PLANES 4           // D_DIM / CHUNK
#define MAX_TYP  2048
#define MAX_ENT  262144
#define MAX_E2   131072

__device__ float              g_typ[MAX_TYP * D_DIM]; // updated type table
__device__ int                g_dst[MAX_ENT];         // per-entity output row
__device__ unsigned long long g_pack[MAX_ENT];        // packed row3 indices
__device__ int                g_src[MAX_E2];          // resolved sub2 sources
__device__ int                g_notid;                // 1 if g_dst[e] != e

__global__ void flag_zero_kernel() { g_notid = 0; }

// ---------------------------------------------------------------------------
// Precompute 1: dst row id + identity detection + packed row indices.
// ---------------------------------------------------------------------------
__global__ void __launch_bounds__(256)
dst_precompute_kernel(const int* __restrict__ s3col,
                      const int* __restrict__ s3row,
                      const int* __restrict__ right_spec,
                      int n_seg, int deg3, int do_pack)
{
    const int e = blockIdx.x * blockDim.x + threadIdx.x;
    if (e >= n_seg) return;

    const long base = (long)e * deg3;
    const int  d    = __ldg(&right_spec[__ldg(&s3col[base])]);
    g_dst[e] = d;
    if (d != e) atomicOr(&g_notid, 1);

    if (do_pack) {                       // deg3==4 && n_typ<=1024
        const int4 r = __ldg((const int4*)(s3row + base));
        g_pack[e] = (unsigned long long)(unsigned)r.x
                  | ((unsigned long long)(unsigned)r.y << 10)
                  | ((unsigned long long)(unsigned)r.z << 20)
                  | ((unsigned long long)(unsigned)r.w << 30);
    }
}

// ---------------------------------------------------------------------------
// Precompute 2: resolved sub2 source ids.
// ---------------------------------------------------------------------------
__global__ void __launch_bounds__(256)
src_precompute_kernel(const int* __restrict__ s2row,
                      const int* __restrict__ left_spec,
                      int n_e2)
{
    const int j = blockIdx.x * blockDim.x + threadIdx.x;
    if (j < n_e2)
        g_src[j] = __ldg(&left_spec[__ldg(&s2row[j])]);
}

// ---------------------------------------------------------------------------
// Kernel A: one block (256 thr = 8 warps) per sub2 segment.
// Each warp gathers whole 128-float rows as float4 (lane = float4 slot) for
// rows j = warp, warp+8, ...; partials reduced through smem; warp 0 finishes.
// ---------------------------------------------------------------------------
__global__ void __launch_bounds__(256)
type_update_kernel(const float* __restrict__ emb,
                   const int*   __restrict__ s2row,
                   const int*   __restrict__ s2col,
                   const int*   __restrict__ left_spec,
                   const int*   __restrict__ right_com,
                   float*       __restrict__ out,
                   int deg2, float n_ent_f, int use_gsrc)
{
    __shared__ float4 part[8][32];

    const int  seg  = blockIdx.x;
    const int  lane = threadIdx.x & 31;
    const int  w    = threadIdx.x >> 5;          // 0..7
    const long base = (long)seg * deg2;
    const int  c    = __ldg(&s2col[base]);

    const float4* __restrict__ emb4 = (const float4*)emb;

    float4 acc = make_float4(0.f, 0.f, 0.f, 0.f);
    if (use_gsrc) {
#pragma unroll 8
        for (int j = w; j < deg2; j += 8) {
            const int src = __ldg(&g_src[base + j]);
            const float4 t = __ldg(&emb4[src * 32 + lane]);
            acc.x += t.x; acc.y += t.y; acc.z += t.z; acc.w += t.w;
        }
    } else {
#pragma unroll 4
        for (int j = w; j < deg2; j += 8) {
            const int src = __ldg(&left_spec[__ldg(&s2row[base + j])]);
            const float4 t = __ldg(&emb4[src * 32 + lane]);
            acc.x += t.x; acc.y += t.y; acc.z += t.z; acc.w += t.w;
        }
    }
    part[w][lane] = acc;
    __syncthreads();

    if (w == 0) {
        float4 s = part[0][lane];
#pragma unroll
        for (int k = 1; k < 8; ++k) {
            const float4 p = part[k][lane];
            s.x += p.x; s.y += p.y; s.z += p.z; s.w += p.w;
        }
        const int   dst = __ldg(&right_com[c]);
        const float add = n_ent_f - (float)deg2;
        const float4 ev = __ldg(&emb4[dst * 32 + lane]);
        float4 v;
        v.x = ev.x + s.x + add;  v.y = ev.y + s.y + add;
        v.z = ev.z + s.z + add;  v.w = ev.w + s.w + add;
        ((float4*)out)[dst * 32 + lane]  = v;
        ((float4*)g_typ)[c * 32 + lane]  = v;
    }
}

// ---------------------------------------------------------------------------
// Kernel B: grid=(gx, 4 planes), 1024 threads, smem = n_typ*32 floats
// (128 KB, 1 block/SM). Vectorized: sub = lane>>3 picks 1 of 4 entities,
// el4 = lane&7 picks the float4 within the 32-float plane. Per warp-iteration
// 8 entities: 2 pack loads, 2 emb LDG.128 (default caching -> L2-resident
// across replays), 8 LDS.128, 2 STG.128 (__stcs, evict-first).
// emb/out addresses are pure loop functions on the identity fast path.
// ---------------------------------------------------------------------------
__global__ void __launch_bounds__(1024)
entity_update_kernel(const float* __restrict__ emb,
                     const int*   __restrict__ s3row,
                     float*       __restrict__ out,
                     int n_seg, int deg3, int n_typ,
                     float addc, float inv_sumarr,
                     int fast8_id, int fast4)
{
    extern __shared__ float styp[];          // n_typ * CHUNK floats

    const int chunk = blockIdx.y;            // 0..3
    const int tid   = threadIdx.x;

    // Stage type-table plane: contiguous 128 B piece per type row.
    const int total = n_typ * CHUNK;
    for (int i = tid; i < total; i += blockDim.x) {
        const int r  = i >> 5;
        const int cc = i & 31;
        styp[i] = g_typ[r * D_DIM + chunk * CHUNK + cc];
    }
    __syncthreads();

    const int lane   = tid & 31;
    const int wid    = tid >> 5;
    const int nwarps = blockDim.x >> 5;
    const int gw     = blockIdx.x * nwarps + wid;
    const int stride = gridDim.x * nwarps;

    if (fast8_id && g_notid == 0) {
        const int sub = lane >> 3;           // entity within 4-group
        const int el4 = lane & 7;            // float4 slot within 32-float plane
        const float4* __restrict__ emb4 = (const float4*)emb;
        float4*       __restrict__ out4 = (float4*)out;
        const float4* __restrict__ st4  = (const float4*)styp;

        // float4 index of (entity e, plane chunk, slot el4): e*32 + chunk*8 + el4
        const int vbase = chunk * 8 + el4;

        const int n_oct = n_seg >> 3;        // 8 entities per warp-iteration
        for (int q = gw; q < n_oct; q += stride) {
            const int e0 = q << 3;
            const int eA = e0 + sub;         // group A entity
            const int eB = e0 + 4 + sub;     // group B entity

            const unsigned long long pA = __ldg(&g_pack[eA]);
            const unsigned long long pB = __ldg(&g_pack[eB]);

            const int oA = eA * 32 + vbase;
            const int oB = eB * 32 + vbase;
            const float4 vA = __ldg(&emb4[oA]);   // cacheable: L2-resident
            const float4 vB = __ldg(&emb4[oB]);

#define ST4(P,SH) st4[(int)(((P) >> SH) & 1023u) * 8 + el4]
            const float4 a0 = ST4(pA, 0),  a1 = ST4(pA, 10),
                         a2 = ST4(pA, 20), a3 = ST4(pA, 30);
            const float4 b0 = ST4(pB, 0),  b1 = ST4(pB, 10),
                         b2 = ST4(pB, 20), b3 = ST4(pB, 30);
#undef ST4
            float4 sA, sB;
            sA.x = addc + a0.x + a1.x + a2.x + a3.x;
            sA.y = addc + a0.y + a1.y + a2.y + a3.y;
            sA.z = addc + a0.z + a1.z + a2.z + a3.z;
            sA.w = addc + a0.w + a1.w + a2.w + a3.w;
            sB.x = addc + b0.x + b1.x + b2.x + b3.x;
            sB.y = addc + b0.y + b1.y + b2.y + b3.y;
            sB.z = addc + b0.z + b1.z + b2.z + b3.z;
            sB.w = addc + b0.w + b1.w + b2.w + b3.w;

            float4 rA, rB;
            rA.x = vA.x * (1.0f - sA.x * inv_sumarr);
            rA.y = vA.y * (1.0f - sA.y * inv_sumarr);
            rA.z = vA.z * (1.0f - sA.z * inv_sumarr);
            rA.w = vA.w * (1.0f - sA.w * inv_sumarr);
            rB.x = vB.x * (1.0f - sB.x * inv_sumarr);
            rB.y = vB.y * (1.0f - sB.y * inv_sumarr);
            rB.z = vB.z * (1.0f - sB.z * inv_sumarr);
            rB.w = vB.w * (1.0f - sB.w * inv_sumarr);

            __stcs(&out4[oA], rA);
            __stcs(&out4[oB], rB);
        }
    } else if (fast4) {
        // Proven scalar 4-wide path with g_dst gather (CHUNK=32 layout).
        const int dbase = chunk * CHUNK + lane;
        const int4* __restrict__ s3row4 = (const int4*)s3row;
        const int4* __restrict__ dst4p  = (const int4*)g_dst;

        const int n_grp = n_seg >> 2;
        for (int g = gw; g < n_grp; g += stride) {
            const int e0 = g << 2;
            const int4 dd = __ldg(&dst4p[g]);
            const int4 r0 = __ldg(&s3row4[e0 + 0]);
            const int4 r1 = __ldg(&s3row4[e0 + 1]);
            const int4 r2 = __ldg(&s3row4[e0 + 2]);
            const int4 r3 = __ldg(&s3row4[e0 + 3]);

            const int o0 = dd.x * D_DIM + dbase;
            const int o1 = dd.y * D_DIM + dbase;
            const int o2 = dd.z * D_DIM + dbase;
            const int o3 = dd.w * D_DIM + dbase;
            const float v0 = __ldg(&emb[o0]);
            const float v1 = __ldg(&emb[o1]);
            const float v2 = __ldg(&emb[o2]);
            const float v3 = __ldg(&emb[o3]);

            const float s0 = addc + styp[r0.x * CHUNK + lane] + styp[r0.y * CHUNK + lane]
                                  + styp[r0.z * CHUNK + lane] + styp[r0.w * CHUNK + lane];
            const float s1 = addc + styp[r1.x * CHUNK + lane] + styp[r1.y * CHUNK + lane]
                                  + styp[r1.z * CHUNK + lane] + styp[r1.w * CHUNK + lane];
            const float s2 = addc + styp[r2.x * CHUNK + lane] + styp[r2.y * CHUNK + lane]
                                  + styp[r2.z * CHUNK + lane] + styp[r2.w * CHUNK + lane];
            const float s3 = addc + styp[r3.x * CHUNK + lane] + styp[r3.y * CHUNK + lane]
                                  + styp[r3.z * CHUNK + lane] + styp[r3.w * CHUNK + lane];

            __stcs(&out[o0], v0 * (1.0f - s0 * inv_sumarr));
            __stcs(&out[o1], v1 * (1.0f - s1 * inv_sumarr));
            __stcs(&out[o2], v2 * (1.0f - s2 * inv_sumarr));
            __stcs(&out[o3], v3 * (1.0f - s3 * inv_sumarr));
        }
    } else {
        // Fully generic fallback.
        const int dbase = chunk * CHUNK + lane;
        for (int e = gw; e < n_seg; e += stride) {
            const long base = (long)e * deg3;
            const int  dst  = g_dst[e];
            float s = addc;
            for (int j = 0; j < deg3; ++j)
                s += styp[__ldg(&s3row[base + j]) * CHUNK + lane];
            const long off = (long)dst * D_DIM + dbase;
            __stcs(&out[off], __ldg(&emb[off]) * (1.0f - s * inv_sumarr));
        }
    }
}

// ---------------------------------------------------------------------------
// Inputs (metadata order):
//   0 all_node_embedding f32   1 sub2_row i32   2 sub2_col i32
//   3 sub3_row i32   4 sub3_col i32   5 left_specific i32 [n_ent]
//   6 right_common i32 [n_typ]   7 left_common i32 [n_typ]
//   8 right_specific i32 [n_ent]
// ---------------------------------------------------------------------------
extern "C" void kernel_launch(void* const* d_in, const int* in_sizes, int n_in,
                              void* d_out, int out_size)
{
    const float* emb        = (const float*)d_in[0];
    const int*   s2row      = (const int*)  d_in[1];
    const int*   s2col      = (const int*)  d_in[2];
    const int*   s3row      = (const int*)  d_in[3];
    const int*   s3col      = (const int*)  d_in[4];
    const int*   left_spec  = (const int*)  d_in[5];
    const int*   right_com  = (const int*)  d_in[6];
    const int*   right_spec = (const int*)  d_in[8];
    float*       out        = (float*)d_out;

    const int n_ent  = in_sizes[5];
    const int n_typ  = in_sizes[7];
    const int n_e2   = in_sizes[1];
    const int deg2   = n_e2 / n_typ;
    const int deg3   = in_sizes[3] / n_ent;
    const int n_seg2 = n_e2 / deg2;          // == n_typ
    const int n_seg3 = in_sizes[3] / deg3;   // == n_ent

    const int use_gsrc = (n_e2 <= MAX_E2);
    const int do_pack  = (deg3 == 4) && (n_typ <= 1024) && (n_seg3 <= MAX_ENT);
    const int fast8_id = do_pack && ((n_seg3 & 7) == 0);
    const int fast4    = (deg3 == 4) && ((n_seg3 & 3) == 0);

    // Precompute chain (stream-ordered): flag zero -> dst/pack/detect -> src.
    flag_zero_kernel<<<1, 1>>>();
    dst_precompute_kernel<<<(n_seg3 + 255) / 256, 256>>>(s3col, s3row, right_spec,
                                                         n_seg3, deg3, do_pack);
    if (use_gsrc)
        src_precompute_kernel<<<(n_e2 + 255) / 256, 256>>>(s2row, left_spec, n_e2);

    // Phase A: type rows (8 warps/segment, float4 whole-row gathers)
    type_update_kernel<<<n_seg2, 256>>>(emb, s2row, s2col, left_spec, right_com,
                                        out, deg2, (float)n_ent, use_gsrc);

    // Phase B: entity rows (4 planes, 1 block/SM, CHUNK=32 conflict-free)
    int sm = 0;
    if (cudaDeviceGetAttribute(&sm, cudaDevAttrMultiProcessorCount, 0) != cudaSuccess
        || sm <= 0)
        sm = 148;
    int gx = sm / N_PLANES; if (gx < 1) gx = 1;

    const size_t smem = (size_t)n_typ * CHUNK * sizeof(float);
    (void)cudaFuncSetAttribute(entity_update_kernel,
                               cudaFuncAttributeMaxDynamicSharedMemorySize,
                               160 * 1024);

    const float addc       = (float)n_typ - (float)deg3;
    const float inv_sumarr = 1.0f / (1.0f + (float)deg3);

    entity_update_kernel<<<dim3(gx, N_PLANES), 1024, smem>>>(emb, s3row, out,
                                                             n_seg3, deg3, n_typ,
                                                             addc, inv_sumarr,
                                                             fast8_id, fast4);
}